// round 1
// baseline (speedup 1.0000x reference)
#include <cuda_runtime.h>

// Problem constants
#define S_   1024
#define B_   8
#define D_   1024
#define H_   16
#define HD_  64
#define T_   (B_ * S_)      // 8192 tokens

// Scratch (device globals: allocation-free per harness rules)
__device__ float g_qkv[(size_t)T_ * 3 * D_];     // [t][3*D]  q|k|v
__device__ float g_attn[(size_t)T_ * D_];        // attention output [t][h*64+d]
__device__ float g_attnout[(size_t)T_ * D_];     // out-proj result
__device__ float g_m[B_ * H_ * S_];              // row max
__device__ float g_linv[B_ * H_ * S_];           // 1 / row sum

// ---------------------------------------------------------------------------
// GEMM: C[M,N] = A[M,K] @ B[N,K]^T + bias[N]   (both A and B K-contiguous)
// 128x128 tile, BK=8, 256 threads, 8x8 micro-tile
// ---------------------------------------------------------------------------
__global__ void __launch_bounds__(256) gemm_nt_kernel(
    const float* __restrict__ A, const float* __restrict__ Bm,
    const float* __restrict__ bias, float* __restrict__ C,
    int M, int N, int K)
{
    __shared__ float As[8][128];
    __shared__ float Bs[8][128];
    const int tid = threadIdx.x;
    const int m0 = blockIdx.y * 128;
    const int n0 = blockIdx.x * 128;
    const int ty = tid >> 4;        // 0..15  -> m sub-tile
    const int tx = tid & 15;        // 0..15  -> n sub-tile
    const int lr = tid >> 1;        // 0..127 load row
    const int lk = (tid & 1) * 4;   // 0 or 4 load k offset
    const float* Ap = A  + (size_t)(m0 + lr) * K + lk;
    const float* Bp = Bm + (size_t)(n0 + lr) * K + lk;

    float acc[8][8];
#pragma unroll
    for (int i = 0; i < 8; i++)
#pragma unroll
        for (int j = 0; j < 8; j++) acc[i][j] = 0.f;

    for (int k0 = 0; k0 < K; k0 += 8) {
        float4 av = *(const float4*)(Ap + k0);
        float4 bv = *(const float4*)(Bp + k0);
        __syncthreads();
        As[lk + 0][lr] = av.x; As[lk + 1][lr] = av.y;
        As[lk + 2][lr] = av.z; As[lk + 3][lr] = av.w;
        Bs[lk + 0][lr] = bv.x; Bs[lk + 1][lr] = bv.y;
        Bs[lk + 2][lr] = bv.z; Bs[lk + 3][lr] = bv.w;
        __syncthreads();
#pragma unroll
        for (int kk = 0; kk < 8; kk++) {
            float a[8], b[8];
            *(float4*)&a[0] = *(const float4*)&As[kk][ty * 8];
            *(float4*)&a[4] = *(const float4*)&As[kk][ty * 8 + 4];
            *(float4*)&b[0] = *(const float4*)&Bs[kk][tx * 8];
            *(float4*)&b[4] = *(const float4*)&Bs[kk][tx * 8 + 4];
#pragma unroll
            for (int i = 0; i < 8; i++)
#pragma unroll
                for (int j = 0; j < 8; j++) acc[i][j] += a[i] * b[j];
        }
    }

#pragma unroll
    for (int i = 0; i < 8; i++) {
        int m = m0 + ty * 8 + i;
#pragma unroll
        for (int j = 0; j < 8; j += 4) {
            int n = n0 + tx * 8 + j;
            float4 o;
            o.x = acc[i][j + 0] + bias[n + 0];
            o.y = acc[i][j + 1] + bias[n + 1];
            o.z = acc[i][j + 2] + bias[n + 2];
            o.w = acc[i][j + 3] + bias[n + 3];
            *(float4*)(C + (size_t)m * N + n) = o;
        }
    }
}

// ---------------------------------------------------------------------------
// Flash attention (online softmax). One block = (b, h, q-tile of 64).
// 128 threads: ty (0..7) -> 8 queries, tx (0..15) -> 4 keys (scores) / 4 dims (AV)
// Writes g_attn, and per-row stats (m, 1/l) for the weights kernel.
// ---------------------------------------------------------------------------
__global__ void __launch_bounds__(128) flash_kernel(const float* __restrict__ td_ptr)
{
    __shared__ float Qs[64 * 64];
    __shared__ float Ks[64 * 64];   // reused as P after scores
    __shared__ float Vs[64 * 64];

    const int tid = threadIdx.x;
    const int bh = blockIdx.x;            // 0..127
    const int qt = blockIdx.y;            // 0..15
    const int b  = bh >> 4;
    const int h  = bh & 15;
    const int tx = tid & 15;
    const int ty = tid >> 4;
    const float atd = fabsf(*td_ptr);
    const float scale = 0.125f;           // 1/sqrt(64)

    // Load Q tile (natural layout Qs[q][d])
    {
        const float* qbase = g_qkv + (size_t)(b * S_ + qt * 64) * (3 * D_) + h * HD_;
#pragma unroll
        for (int l = 0; l < 8; l++) {
            int lin = tid + l * 128;
            int r = lin >> 4;
            int d4 = (lin & 15) * 4;
            *(float4*)&Qs[r * 64 + d4] = *(const float4*)(qbase + (size_t)r * (3 * D_) + d4);
        }
    }

    float m[8], lsum[8], acc[8][4];
#pragma unroll
    for (int qi = 0; qi < 8; qi++) {
        m[qi] = -1e30f; lsum[qi] = 0.f;
#pragma unroll
        for (int j = 0; j < 4; j++) acc[qi][j] = 0.f;
    }

    for (int kt = 0; kt < 16; kt++) {
        const float* kbase = g_qkv + (size_t)(b * S_ + kt * 64) * (3 * D_) + D_ + h * HD_;
        const float* vbase = kbase + D_;
        __syncthreads();   // previous iter finished reading Ks(P)/Vs
#pragma unroll
        for (int l = 0; l < 8; l++) {
            int lin = tid + l * 128;
            int r = lin >> 4;
            int u = lin & 15;   // 16B unit
            float4 kv = *(const float4*)(kbase + (size_t)r * (3 * D_) + u * 4);
            float4 vv = *(const float4*)(vbase + (size_t)r * (3 * D_) + u * 4);
            *(float4*)&Ks[r * 64 + ((u ^ (r & 15)) << 2)] = kv;   // XOR-swizzled
            *(float4*)&Vs[r * 64 + u * 4] = vv;
        }
        __syncthreads();

        // Scores s[8q][4k]
        float s[8][4];
#pragma unroll
        for (int qi = 0; qi < 8; qi++)
#pragma unroll
            for (int j = 0; j < 4; j++) s[qi][j] = 0.f;

#pragma unroll
        for (int d4 = 0; d4 < 64; d4 += 4) {
            int u = d4 >> 2;
            float4 kf[4];
#pragma unroll
            for (int i = 0; i < 4; i++) {
                int krow = tx * 4 + i;
                kf[i] = *(const float4*)&Ks[krow * 64 + ((u ^ (krow & 15)) << 2)];
            }
#pragma unroll
            for (int qi = 0; qi < 8; qi++) {
                float4 qf = *(const float4*)&Qs[(ty * 8 + qi) * 64 + d4];
#pragma unroll
                for (int i = 0; i < 4; i++) {
                    s[qi][i] += qf.x * kf[i].x + qf.y * kf[i].y +
                                qf.z * kf[i].z + qf.w * kf[i].w;
                }
            }
        }

        __syncthreads();   // all threads done reading Ks -> safe to overwrite with P

        // bias + scale + online softmax
#pragma unroll
        for (int qi = 0; qi < 8; qi++) {
            int qg = qt * 64 + ty * 8 + qi;
            float mloc = -1e30f;
#pragma unroll
            for (int i = 0; i < 4; i++) {
                int kg = kt * 64 + tx * 4 + i;
                float val = s[qi][i] * scale - atd * fabsf((float)(qg - kg));
                s[qi][i] = val;
                mloc = fmaxf(mloc, val);
            }
#pragma unroll
            for (int o = 8; o >= 1; o >>= 1)
                mloc = fmaxf(mloc, __shfl_xor_sync(0xffffffffu, mloc, o));
            float mnew = fmaxf(m[qi], mloc);
            float corr = __expf(m[qi] - mnew);
            lsum[qi] *= corr;
#pragma unroll
            for (int j = 0; j < 4; j++) acc[qi][j] *= corr;
            float psum = 0.f;
#pragma unroll
            for (int i = 0; i < 4; i++) {
                float p = __expf(s[qi][i] - mnew);
                s[qi][i] = p;
                psum += p;
            }
#pragma unroll
            for (int o = 8; o >= 1; o >>= 1)
                psum += __shfl_xor_sync(0xffffffffu, psum, o);
            lsum[qi] += psum;
            m[qi] = mnew;
#pragma unroll
            for (int i = 0; i < 4; i++)
                Ks[(ty * 8 + qi) * 64 + tx * 4 + i] = s[qi][i];   // P (natural layout)
        }
        __syncthreads();

        // AV: acc[q][d] += P[q][k] * V[k][d]
#pragma unroll
        for (int k4 = 0; k4 < 64; k4 += 4) {
            float4 vf[4];
#pragma unroll
            for (int i = 0; i < 4; i++)
                vf[i] = *(const float4*)&Vs[(k4 + i) * 64 + tx * 4];
#pragma unroll
            for (int qi = 0; qi < 8; qi++) {
                float4 pf = *(const float4*)&Ks[(ty * 8 + qi) * 64 + k4];
                acc[qi][0] += pf.x * vf[0].x + pf.y * vf[1].x + pf.z * vf[2].x + pf.w * vf[3].x;
                acc[qi][1] += pf.x * vf[0].y + pf.y * vf[1].y + pf.z * vf[2].y + pf.w * vf[3].y;
                acc[qi][2] += pf.x * vf[0].z + pf.y * vf[1].z + pf.z * vf[2].z + pf.w * vf[3].z;
                acc[qi][3] += pf.x * vf[0].w + pf.y * vf[1].w + pf.z * vf[2].w + pf.w * vf[3].w;
            }
        }
    }

    // Epilogue: normalize, write output + stats
#pragma unroll
    for (int qi = 0; qi < 8; qi++) {
        float inv = 1.f / lsum[qi];
        int t = b * S_ + qt * 64 + ty * 8 + qi;
        float4 o4;
        o4.x = acc[qi][0] * inv; o4.y = acc[qi][1] * inv;
        o4.z = acc[qi][2] * inv; o4.w = acc[qi][3] * inv;
        *(float4*)&g_attn[(size_t)t * D_ + h * HD_ + tx * 4] = o4;
        if (tx == 0) {
            int si = (b * H_ + h) * S_ + qt * 64 + ty * 8 + qi;
            g_m[si] = m[qi];
            g_linv[si] = inv;
        }
    }
}

// ---------------------------------------------------------------------------
// Head-mean attention weights. One block = (qt, b, kt). Loops over heads,
// recomputes scores, normalizes with saved (m, 1/l), writes mean over heads.
// ---------------------------------------------------------------------------
__global__ void __launch_bounds__(128) weights_kernel(
    const float* __restrict__ td_ptr, float* __restrict__ wout)
{
    __shared__ float Qs[64 * 64];
    __shared__ float Ks[64 * 64];

    const int tid = threadIdx.x;
    const int qt = blockIdx.x;   // 0..15
    const int b  = blockIdx.y;   // 0..7
    const int kt = blockIdx.z;   // 0..15
    const int tx = tid & 15;
    const int ty = tid >> 4;
    const float atd = fabsf(*td_ptr);
    const float scale = 0.125f;

    float wsum[8][4];
#pragma unroll
    for (int qi = 0; qi < 8; qi++)
#pragma unroll
        for (int i = 0; i < 4; i++) wsum[qi][i] = 0.f;

    for (int h = 0; h < H_; h++) {
        const float* qbase = g_qkv + (size_t)(b * S_ + qt * 64) * (3 * D_) + h * HD_;
        const float* kbase = g_qkv + (size_t)(b * S_ + kt * 64) * (3 * D_) + D_ + h * HD_;
        __syncthreads();
#pragma unroll
        for (int l = 0; l < 8; l++) {
            int lin = tid + l * 128;
            int r = lin >> 4;
            int u = lin & 15;
            *(float4*)&Qs[r * 64 + u * 4] =
                *(const float4*)(qbase + (size_t)r * (3 * D_) + u * 4);
            *(float4*)&Ks[r * 64 + ((u ^ (r & 15)) << 2)] =
                *(const float4*)(kbase + (size_t)r * (3 * D_) + u * 4);
        }
        __syncthreads();

        float s[8][4];
#pragma unroll
        for (int qi = 0; qi < 8; qi++)
#pragma unroll
            for (int j = 0; j < 4; j++) s[qi][j] = 0.f;

#pragma unroll
        for (int d4 = 0; d4 < 64; d4 += 4) {
            int u = d4 >> 2;
            float4 kf[4];
#pragma unroll
            for (int i = 0; i < 4; i++) {
                int krow = tx * 4 + i;
                kf[i] = *(const float4*)&Ks[krow * 64 + ((u ^ (krow & 15)) << 2)];
            }
#pragma unroll
            for (int qi = 0; qi < 8; qi++) {
                float4 qf = *(const float4*)&Qs[(ty * 8 + qi) * 64 + d4];
#pragma unroll
                for (int i = 0; i < 4; i++) {
                    s[qi][i] += qf.x * kf[i].x + qf.y * kf[i].y +
                                qf.z * kf[i].z + qf.w * kf[i].w;
                }
            }
        }

#pragma unroll
        for (int qi = 0; qi < 8; qi++) {
            int qg = qt * 64 + ty * 8 + qi;
            int si = (b * H_ + h) * S_ + qg;
            float mq = g_m[si];
            float il = g_linv[si];
#pragma unroll
            for (int i = 0; i < 4; i++) {
                int kg = kt * 64 + tx * 4 + i;
                float val = s[qi][i] * scale - atd * fabsf((float)(qg - kg));
                wsum[qi][i] += __expf(val - mq) * il;
            }
        }
    }

    const float inv_h = 1.0f / (float)H_;
#pragma unroll
    for (int qi = 0; qi < 8; qi++) {
        int qg = qt * 64 + ty * 8 + qi;
        float4 w4;
        w4.x = wsum[qi][0] * inv_h; w4.y = wsum[qi][1] * inv_h;
        w4.z = wsum[qi][2] * inv_h; w4.w = wsum[qi][3] * inv_h;
        *(float4*)(wout + ((size_t)(b * S_ + qg)) * S_ + kt * 64 + tx * 4) = w4;
    }
}

// ---------------------------------------------------------------------------
// Residual + LayerNorm. One block per token row.
// ---------------------------------------------------------------------------
__global__ void __launch_bounds__(256) ln_kernel(
    const float* __restrict__ x, const float* __restrict__ lnw,
    const float* __restrict__ lnb, float* __restrict__ out)
{
    const int row = blockIdx.x;
    const int tid = threadIdx.x;
    const float* xr = x + (size_t)row * D_;
    const float* ar = g_attnout + (size_t)row * D_;

    float4 xv = *(const float4*)(xr + tid * 4);
    float4 av = *(const float4*)(ar + tid * 4);
    float y[4];
    y[0] = xv.x + av.x; y[1] = xv.y + av.y;
    y[2] = xv.z + av.z; y[3] = xv.w + av.w;

    float s  = y[0] + y[1] + y[2] + y[3];
    float sq = y[0]*y[0] + y[1]*y[1] + y[2]*y[2] + y[3]*y[3];
#pragma unroll
    for (int o = 16; o >= 1; o >>= 1) {
        s  += __shfl_xor_sync(0xffffffffu, s,  o);
        sq += __shfl_xor_sync(0xffffffffu, sq, o);
    }
    __shared__ float red[16];
    const int wid = tid >> 5;
    if ((tid & 31) == 0) { red[wid] = s; red[8 + wid] = sq; }
    __syncthreads();
    float st = 0.f, sqt = 0.f;
#pragma unroll
    for (int w = 0; w < 8; w++) { st += red[w]; sqt += red[8 + w]; }
    float mu = st * (1.0f / D_);
    float var = sqt * (1.0f / D_) - mu * mu;
    float rstd = rsqrtf(var + 1e-5f);

    float4 wv = *(const float4*)(lnw + tid * 4);
    float4 bv = *(const float4*)(lnb + tid * 4);
    float4 o4;
    o4.x = (y[0] - mu) * rstd * wv.x + bv.x;
    o4.y = (y[1] - mu) * rstd * wv.y + bv.y;
    o4.z = (y[2] - mu) * rstd * wv.z + bv.z;
    o4.w = (y[3] - mu) * rstd * wv.w + bv.w;
    *(float4*)(out + (size_t)row * D_ + tid * 4) = o4;
}

// ---------------------------------------------------------------------------
extern "C" void kernel_launch(void* const* d_in, const int* in_sizes, int n_in,
                              void* d_out, int out_size)
{
    (void)in_sizes; (void)n_in; (void)out_size;
    const float* x     = (const float*)d_in[0];
    const float* td    = (const float*)d_in[1];
    const float* in_w  = (const float*)d_in[2];
    const float* in_b  = (const float*)d_in[3];
    const float* out_w = (const float*)d_in[4];
    const float* out_b = (const float*)d_in[5];
    const float* lnw   = (const float*)d_in[6];
    const float* lnb   = (const float*)d_in[7];
    float* out  = (float*)d_out;
    float* wout = out + (size_t)T_ * D_;   // second tuple element: attn_weights [B,S,S]

    float *qkv_p, *attn_p, *attnout_p;
    cudaGetSymbolAddress((void**)&qkv_p, g_qkv);
    cudaGetSymbolAddress((void**)&attn_p, g_attn);
    cudaGetSymbolAddress((void**)&attnout_p, g_attnout);

    // 1. QKV = x @ in_proj_w^T + in_proj_b   [8192, 3072]
    gemm_nt_kernel<<<dim3(3 * D_ / 128, T_ / 128), 256>>>(
        x, in_w, in_b, qkv_p, T_, 3 * D_, D_);

    // 2. Flash attention -> g_attn, stats
    flash_kernel<<<dim3(B_ * H_, S_ / 64), 128>>>(td);

    // 3. Head-mean weights -> second output
    weights_kernel<<<dim3(S_ / 64, B_, S_ / 64), 128>>>(td, wout);

    // 4. attn_out = attn @ out_proj_w^T + out_proj_b  [8192, 1024]
    gemm_nt_kernel<<<dim3(D_ / 128, T_ / 128), 256>>>(
        attn_p, out_w, out_b, attnout_p, T_, D_, D_);

    // 5. Residual + LayerNorm -> first output
    ln_kernel<<<T_, 256>>>(x, lnw, lnb, out);
}

// round 2
// speedup vs baseline: 1.3189x; 1.3189x over previous
#include <cuda_runtime.h>

// Problem constants
#define S_   1024
#define B_   8
#define D_   1024
#define H_   16
#define HD_  64
#define T_   (B_ * S_)      // 8192 tokens
#define D3_  (3 * D_)

// Scratch (device globals: allocation-free per harness rules)
__device__ float g_qkv[(size_t)T_ * 3 * D_];     // [t][3*D]  q|k|v
__device__ float g_attn[(size_t)T_ * D_];        // attention output
__device__ float g_attnout[(size_t)T_ * D_];     // out-proj result
__device__ float g_m[B_ * H_ * S_];              // row max
__device__ float g_linv[B_ * H_ * S_];           // 1 / row sum

__device__ __forceinline__ unsigned su32(const void* p) {
    return (unsigned)__cvta_generic_to_shared(p);
}
__device__ __forceinline__ void cpa16(unsigned dst, const float* src) {
    asm volatile("cp.async.cg.shared.global [%0], [%1], 16;" :: "r"(dst), "l"(src));
}
#define CP_COMMIT() asm volatile("cp.async.commit_group;")
#define CP_WAIT0()  asm volatile("cp.async.wait_group 0;")

// ---------------------------------------------------------------------------
// GEMM: C[M,N] = A[M,K] @ B[N,K]^T + bias[N]
// 128x128 tile, BK=8, 256 threads, 8x8 micro-tile, double-buffered smem.
// Thread columns: tx*4..tx*4+3 and 64+tx*4..64+tx*4+3 (conflict-free LDS).
// ---------------------------------------------------------------------------
__global__ void __launch_bounds__(256) gemm_nt_kernel(
    const float* __restrict__ A, const float* __restrict__ Bm,
    const float* __restrict__ bias, float* __restrict__ C,
    int M, int N, int K)
{
    __shared__ float As[2][8][128];
    __shared__ float Bs[2][8][128];
    const int tid = threadIdx.x;
    const int m0 = blockIdx.y * 128;
    const int n0 = blockIdx.x * 128;
    const int ty = tid >> 4;
    const int tx = tid & 15;
    const int lr = tid >> 1;
    const int lk = (tid & 1) * 4;
    const float* Ap = A  + (size_t)(m0 + lr) * K + lk;
    const float* Bp = Bm + (size_t)(n0 + lr) * K + lk;

    float acc[8][8];
#pragma unroll
    for (int i = 0; i < 8; i++)
#pragma unroll
        for (int j = 0; j < 8; j++) acc[i][j] = 0.f;

    float4 av = *(const float4*)(Ap);
    float4 bv = *(const float4*)(Bp);
    int buf = 0;
    As[0][lk + 0][lr] = av.x; As[0][lk + 1][lr] = av.y;
    As[0][lk + 2][lr] = av.z; As[0][lk + 3][lr] = av.w;
    Bs[0][lk + 0][lr] = bv.x; Bs[0][lk + 1][lr] = bv.y;
    Bs[0][lk + 2][lr] = bv.z; Bs[0][lk + 3][lr] = bv.w;
    __syncthreads();

    for (int k0 = 8; k0 <= K; k0 += 8) {
        if (k0 < K) {   // prefetch next slab
            av = *(const float4*)(Ap + k0);
            bv = *(const float4*)(Bp + k0);
        }
#pragma unroll
        for (int kk = 0; kk < 8; kk++) {
            float a[8], b[8];
            *(float4*)&a[0] = *(const float4*)&As[buf][kk][ty * 8];
            *(float4*)&a[4] = *(const float4*)&As[buf][kk][ty * 8 + 4];
            *(float4*)&b[0] = *(const float4*)&Bs[buf][kk][tx * 4];
            *(float4*)&b[4] = *(const float4*)&Bs[buf][kk][64 + tx * 4];
#pragma unroll
            for (int i = 0; i < 8; i++)
#pragma unroll
                for (int j = 0; j < 8; j++) acc[i][j] += a[i] * b[j];
        }
        if (k0 < K) {
            buf ^= 1;
            As[buf][lk + 0][lr] = av.x; As[buf][lk + 1][lr] = av.y;
            As[buf][lk + 2][lr] = av.z; As[buf][lk + 3][lr] = av.w;
            Bs[buf][lk + 0][lr] = bv.x; Bs[buf][lk + 1][lr] = bv.y;
            Bs[buf][lk + 2][lr] = bv.z; Bs[buf][lk + 3][lr] = bv.w;
            __syncthreads();
        }
    }

#pragma unroll
    for (int i = 0; i < 8; i++) {
        int m = m0 + ty * 8 + i;
        int n1 = n0 + tx * 4;
        int n2 = n0 + 64 + tx * 4;
        float4 o1, o2;
        o1.x = acc[i][0] + bias[n1 + 0]; o1.y = acc[i][1] + bias[n1 + 1];
        o1.z = acc[i][2] + bias[n1 + 2]; o1.w = acc[i][3] + bias[n1 + 3];
        o2.x = acc[i][4] + bias[n2 + 0]; o2.y = acc[i][5] + bias[n2 + 1];
        o2.z = acc[i][6] + bias[n2 + 2]; o2.w = acc[i][7] + bias[n2 + 3];
        *(float4*)(C + (size_t)m * N + n1) = o1;
        *(float4*)(C + (size_t)m * N + n2) = o2;
    }
}

// ---------------------------------------------------------------------------
// Flash attention. One block = (b, h, q-tile of 64). 128 threads.
// K/V double-buffered via cp.async. K swizzled (u ^ ((r>>2)&7)).
// Dynamic smem 96KB: Qs[4096] Ks[2][4096] Vs[2][4096] Ps[4096]
// ---------------------------------------------------------------------------
__global__ void __launch_bounds__(128) flash_kernel(const float* __restrict__ td_ptr)
{
    extern __shared__ float sm[];
    float* Qs = sm;                 // 4096
    float* Ksb = sm + 4096;         // 2 x 4096
    float* Vsb = sm + 12288;        // 2 x 4096
    float* Ps = sm + 20480;         // 4096

    const int tid = threadIdx.x;
    const int bh = blockIdx.x;
    const int qt = blockIdx.y;
    const int b  = bh >> 4;
    const int h  = bh & 15;
    const int tx = tid & 15;
    const int ty = tid >> 4;
    const float atd = fabsf(*td_ptr);
    const float scale = 0.125f;

    // Q tile (natural layout)
    {
        const float* qbase = g_qkv + (size_t)(b * S_ + qt * 64) * D3_ + h * HD_;
#pragma unroll
        for (int l = 0; l < 8; l++) {
            int lin = tid + l * 128;
            int r = lin >> 4;
            int u = lin & 15;
            *(float4*)&Qs[r * 64 + u * 4] = *(const float4*)(qbase + (size_t)r * D3_ + u * 4);
        }
    }

    // issue cp.async for K/V tile kt into buffer bf
    auto issue = [&](int kt, int bf) {
        const float* kb = g_qkv + (size_t)(b * S_ + kt * 64) * D3_ + D_ + h * HD_;
        const float* vb = kb + D_;
        float* Kd = Ksb + bf * 4096;
        float* Vd = Vsb + bf * 4096;
#pragma unroll
        for (int l = 0; l < 8; l++) {
            int lin = tid + l * 128;
            int r = lin >> 4;
            int u = lin & 15;
            cpa16(su32(&Kd[r * 64 + ((u ^ ((r >> 2) & 7)) << 2)]), kb + (size_t)r * D3_ + u * 4);
            cpa16(su32(&Vd[r * 64 + u * 4]), vb + (size_t)r * D3_ + u * 4);
        }
        CP_COMMIT();
    };

    issue(0, 0);

    float m[8], lsum[8], acc[8][4];
#pragma unroll
    for (int qi = 0; qi < 8; qi++) {
        m[qi] = -1e30f; lsum[qi] = 0.f;
#pragma unroll
        for (int j = 0; j < 4; j++) acc[qi][j] = 0.f;
    }

    for (int kt = 0; kt < 16; kt++) {
        CP_WAIT0();
        __syncthreads();                  // tile kt ready; prev AV done
        if (kt < 15) issue(kt + 1, (kt + 1) & 1);

        const float* Kc = Ksb + (kt & 1) * 4096;
        const float* Vc = Vsb + (kt & 1) * 4096;

        // Scores s[8q][4k]
        float s[8][4];
#pragma unroll
        for (int qi = 0; qi < 8; qi++)
#pragma unroll
            for (int j = 0; j < 4; j++) s[qi][j] = 0.f;

#pragma unroll
        for (int d4 = 0; d4 < 64; d4 += 4) {
            int u = d4 >> 2;
            float4 kf[4];
#pragma unroll
            for (int i = 0; i < 4; i++)
                kf[i] = *(const float4*)&Kc[(tx * 4 + i) * 64 + ((u ^ (tx & 7)) << 2)];
#pragma unroll
            for (int qi = 0; qi < 8; qi++) {
                float4 qf = *(const float4*)&Qs[(ty * 8 + qi) * 64 + d4];
#pragma unroll
                for (int i = 0; i < 4; i++)
                    s[qi][i] += qf.x * kf[i].x + qf.y * kf[i].y +
                                qf.z * kf[i].z + qf.w * kf[i].w;
            }
        }

        // softmax (online) + write P
#pragma unroll
        for (int qi = 0; qi < 8; qi++) {
            int qg = qt * 64 + ty * 8 + qi;
            float mloc = -1e30f;
#pragma unroll
            for (int i = 0; i < 4; i++) {
                int kg = kt * 64 + tx * 4 + i;
                float val = s[qi][i] * scale - atd * fabsf((float)(qg - kg));
                s[qi][i] = val;
                mloc = fmaxf(mloc, val);
            }
#pragma unroll
            for (int o = 8; o >= 1; o >>= 1)
                mloc = fmaxf(mloc, __shfl_xor_sync(0xffffffffu, mloc, o));
            float mnew = fmaxf(m[qi], mloc);
            float corr = __expf(m[qi] - mnew);
            lsum[qi] *= corr;
#pragma unroll
            for (int j = 0; j < 4; j++) acc[qi][j] *= corr;
            float psum = 0.f;
#pragma unroll
            for (int i = 0; i < 4; i++) {
                float p = __expf(s[qi][i] - mnew);
                s[qi][i] = p;
                psum += p;
            }
#pragma unroll
            for (int o = 8; o >= 1; o >>= 1)
                psum += __shfl_xor_sync(0xffffffffu, psum, o);
            lsum[qi] += psum;
            m[qi] = mnew;
            *(float4*)&Ps[(ty * 8 + qi) * 64 + tx * 4] =
                make_float4(s[qi][0], s[qi][1], s[qi][2], s[qi][3]);
        }
        __syncthreads();                  // P visible

        // AV: acc[q][d(tx*4..)] += P[q][k] * V[k][d]
#pragma unroll
        for (int k4 = 0; k4 < 64; k4 += 4) {
            float4 vf[4];
#pragma unroll
            for (int i = 0; i < 4; i++)
                vf[i] = *(const float4*)&Vc[(k4 + i) * 64 + tx * 4];
#pragma unroll
            for (int qi = 0; qi < 8; qi++) {
                float4 pf = *(const float4*)&Ps[(ty * 8 + qi) * 64 + k4];
                acc[qi][0] += pf.x * vf[0].x + pf.y * vf[1].x + pf.z * vf[2].x + pf.w * vf[3].x;
                acc[qi][1] += pf.x * vf[0].y + pf.y * vf[1].y + pf.z * vf[2].y + pf.w * vf[3].y;
                acc[qi][2] += pf.x * vf[0].z + pf.y * vf[1].z + pf.z * vf[2].z + pf.w * vf[3].z;
                acc[qi][3] += pf.x * vf[0].w + pf.y * vf[1].w + pf.z * vf[2].w + pf.w * vf[3].w;
            }
        }
    }

#pragma unroll
    for (int qi = 0; qi < 8; qi++) {
        float inv = 1.f / lsum[qi];
        int t = b * S_ + qt * 64 + ty * 8 + qi;
        float4 o4;
        o4.x = acc[qi][0] * inv; o4.y = acc[qi][1] * inv;
        o4.z = acc[qi][2] * inv; o4.w = acc[qi][3] * inv;
        *(float4*)&g_attn[(size_t)t * D_ + h * HD_ + tx * 4] = o4;
        if (tx == 0) {
            int si = (b * H_ + h) * S_ + qt * 64 + ty * 8 + qi;
            g_m[si] = m[qi];
            g_linv[si] = inv;
        }
    }
}

// ---------------------------------------------------------------------------
// Head-mean attention weights. One block = (qt, b, kt). cp.async double-
// buffered over the head loop. Dynamic smem 64KB: Qs[2][4096] Ks[2][4096].
// ---------------------------------------------------------------------------
__global__ void __launch_bounds__(128) weights_kernel(
    const float* __restrict__ td_ptr, float* __restrict__ wout)
{
    extern __shared__ float sm[];
    float* Qsb = sm;            // 2 x 4096
    float* Ksb = sm + 8192;     // 2 x 4096

    const int tid = threadIdx.x;
    const int qt = blockIdx.x;
    const int b  = blockIdx.y;
    const int kt = blockIdx.z;
    const int tx = tid & 15;
    const int ty = tid >> 4;
    const float atd = fabsf(*td_ptr);
    const float scale = 0.125f;

    auto issue = [&](int h, int bf) {
        const float* qb = g_qkv + (size_t)(b * S_ + qt * 64) * D3_ + h * HD_;
        const float* kb = g_qkv + (size_t)(b * S_ + kt * 64) * D3_ + D_ + h * HD_;
        float* Qd = Qsb + bf * 4096;
        float* Kd = Ksb + bf * 4096;
#pragma unroll
        for (int l = 0; l < 8; l++) {
            int lin = tid + l * 128;
            int r = lin >> 4;
            int u = lin & 15;
            cpa16(su32(&Qd[r * 64 + u * 4]), qb + (size_t)r * D3_ + u * 4);
            cpa16(su32(&Kd[r * 64 + ((u ^ ((r >> 2) & 7)) << 2)]), kb + (size_t)r * D3_ + u * 4);
        }
        CP_COMMIT();
    };

    issue(0, 0);

    float wsum[8][4];
#pragma unroll
    for (int qi = 0; qi < 8; qi++)
#pragma unroll
        for (int i = 0; i < 4; i++) wsum[qi][i] = 0.f;

    for (int h = 0; h < H_; h++) {
        CP_WAIT0();
        __syncthreads();
        if (h < 15) issue(h + 1, (h + 1) & 1);

        const float* Qc = Qsb + (h & 1) * 4096;
        const float* Kc = Ksb + (h & 1) * 4096;

        float s[8][4];
#pragma unroll
        for (int qi = 0; qi < 8; qi++)
#pragma unroll
            for (int j = 0; j < 4; j++) s[qi][j] = 0.f;

#pragma unroll
        for (int d4 = 0; d4 < 64; d4 += 4) {
            int u = d4 >> 2;
            float4 kf[4];
#pragma unroll
            for (int i = 0; i < 4; i++)
                kf[i] = *(const float4*)&Kc[(tx * 4 + i) * 64 + ((u ^ (tx & 7)) << 2)];
#pragma unroll
            for (int qi = 0; qi < 8; qi++) {
                float4 qf = *(const float4*)&Qc[(ty * 8 + qi) * 64 + d4];
#pragma unroll
                for (int i = 0; i < 4; i++)
                    s[qi][i] += qf.x * kf[i].x + qf.y * kf[i].y +
                                qf.z * kf[i].z + qf.w * kf[i].w;
            }
        }

#pragma unroll
        for (int qi = 0; qi < 8; qi++) {
            int qg = qt * 64 + ty * 8 + qi;
            int si = (b * H_ + h) * S_ + qg;
            float mq = g_m[si];
            float il = g_linv[si];
#pragma unroll
            for (int i = 0; i < 4; i++) {
                int kg = kt * 64 + tx * 4 + i;
                float val = s[qi][i] * scale - atd * fabsf((float)(qg - kg));
                wsum[qi][i] += __expf(val - mq) * il;
            }
        }
    }

    const float inv_h = 1.0f / (float)H_;
#pragma unroll
    for (int qi = 0; qi < 8; qi++) {
        int qg = qt * 64 + ty * 8 + qi;
        float4 w4;
        w4.x = wsum[qi][0] * inv_h; w4.y = wsum[qi][1] * inv_h;
        w4.z = wsum[qi][2] * inv_h; w4.w = wsum[qi][3] * inv_h;
        *(float4*)(wout + ((size_t)(b * S_ + qg)) * S_ + kt * 64 + tx * 4) = w4;
    }
}

// ---------------------------------------------------------------------------
// Residual + LayerNorm. One block per token row.
// ---------------------------------------------------------------------------
__global__ void __launch_bounds__(256) ln_kernel(
    const float* __restrict__ x, const float* __restrict__ lnw,
    const float* __restrict__ lnb, float* __restrict__ out)
{
    const int row = blockIdx.x;
    const int tid = threadIdx.x;
    const float* xr = x + (size_t)row * D_;
    const float* ar = g_attnout + (size_t)row * D_;

    float4 xv = *(const float4*)(xr + tid * 4);
    float4 av = *(const float4*)(ar + tid * 4);
    float y[4];
    y[0] = xv.x + av.x; y[1] = xv.y + av.y;
    y[2] = xv.z + av.z; y[3] = xv.w + av.w;

    float s  = y[0] + y[1] + y[2] + y[3];
    float sq = y[0]*y[0] + y[1]*y[1] + y[2]*y[2] + y[3]*y[3];
#pragma unroll
    for (int o = 16; o >= 1; o >>= 1) {
        s  += __shfl_xor_sync(0xffffffffu, s,  o);
        sq += __shfl_xor_sync(0xffffffffu, sq, o);
    }
    __shared__ float red[16];
    const int wid = tid >> 5;
    if ((tid & 31) == 0) { red[wid] = s; red[8 + wid] = sq; }
    __syncthreads();
    float st = 0.f, sqt = 0.f;
#pragma unroll
    for (int w = 0; w < 8; w++) { st += red[w]; sqt += red[8 + w]; }
    float mu = st * (1.0f / D_);
    float var = sqt * (1.0f / D_) - mu * mu;
    float rstd = rsqrtf(var + 1e-5f);

    float4 wv = *(const float4*)(lnw + tid * 4);
    float4 bv = *(const float4*)(lnb + tid * 4);
    float4 o4;
    o4.x = (y[0] - mu) * rstd * wv.x + bv.x;
    o4.y = (y[1] - mu) * rstd * wv.y + bv.y;
    o4.z = (y[2] - mu) * rstd * wv.z + bv.z;
    o4.w = (y[3] - mu) * rstd * wv.w + bv.w;
    *(float4*)(out + (size_t)row * D_ + tid * 4) = o4;
}

// ---------------------------------------------------------------------------
extern "C" void kernel_launch(void* const* d_in, const int* in_sizes, int n_in,
                              void* d_out, int out_size)
{
    (void)in_sizes; (void)n_in; (void)out_size;
    const float* x     = (const float*)d_in[0];
    const float* td    = (const float*)d_in[1];
    const float* in_w  = (const float*)d_in[2];
    const float* in_b  = (const float*)d_in[3];
    const float* out_w = (const float*)d_in[4];
    const float* out_b = (const float*)d_in[5];
    const float* lnw   = (const float*)d_in[6];
    const float* lnb   = (const float*)d_in[7];
    float* out  = (float*)d_out;
    float* wout = out + (size_t)T_ * D_;   // attn_weights [B,S,S]

    float *qkv_p, *attn_p, *attnout_p;
    cudaGetSymbolAddress((void**)&qkv_p, g_qkv);
    cudaGetSymbolAddress((void**)&attn_p, g_attn);
    cudaGetSymbolAddress((void**)&attnout_p, g_attnout);

    cudaFuncSetAttribute(flash_kernel, cudaFuncAttributeMaxDynamicSharedMemorySize, 96 * 1024);
    cudaFuncSetAttribute(weights_kernel, cudaFuncAttributeMaxDynamicSharedMemorySize, 64 * 1024);

    // 1. QKV = x @ in_proj_w^T + in_proj_b   [8192, 3072]
    gemm_nt_kernel<<<dim3(3 * D_ / 128, T_ / 128), 256>>>(
        x, in_w, in_b, qkv_p, T_, 3 * D_, D_);

    // 2. Flash attention -> g_attn, stats
    flash_kernel<<<dim3(B_ * H_, S_ / 64), 128, 96 * 1024>>>(td);

    // 3. Head-mean weights -> second output
    weights_kernel<<<dim3(S_ / 64, B_, S_ / 64), 128, 64 * 1024>>>(td, wout);

    // 4. attn_out = attn @ out_proj_w^T + out_proj_b  [8192, 1024]
    gemm_nt_kernel<<<dim3(D_ / 128, T_ / 128), 256>>>(
        attn_p, out_w, out_b, attnout_p, T_, D_, D_);

    // 5. Residual + LayerNorm -> first output
    ln_kernel<<<T_, 256>>>(x, lnw, lnb, out);
}

// round 3
// speedup vs baseline: 2.0159x; 1.5285x over previous
#include <cuda_runtime.h>

// Problem constants
#define S_   1024
#define B_   8
#define D_   1024
#define H_   16
#define HD_  64
#define T_   (B_ * S_)      // 8192 tokens
#define D3_  (3 * D_)

// Scratch (device globals)
__device__ float g_qkv[(size_t)T_ * 3 * D_];
__device__ float g_attn[(size_t)T_ * D_];
__device__ float g_attnout[(size_t)T_ * D_];
__device__ float g_m[B_ * H_ * S_];
__device__ float g_linv[B_ * H_ * S_];

__device__ __forceinline__ unsigned su32(const void* p) {
    return (unsigned)__cvta_generic_to_shared(p);
}
__device__ __forceinline__ void cpa16(unsigned dst, const float* src) {
    asm volatile("cp.async.cg.shared.global [%0], [%1], 16;" :: "r"(dst), "l"(src));
}
#define CP_COMMIT() asm volatile("cp.async.commit_group;")
#define CP_WAIT0()  asm volatile("cp.async.wait_group 0;")

__device__ __forceinline__ float f2tf(float x) {
    unsigned r;
    asm("cvt.rna.tf32.f32 %0, %1;" : "=r"(r) : "f"(x));
    return __uint_as_float(r);
}
__device__ __forceinline__ unsigned ftou(float x) { return __float_as_uint(x); }

// d = a@b + c   (m16n8k8 tf32)
__device__ __forceinline__ void mma8(float* d, const unsigned* a, const unsigned* b) {
    asm volatile(
        "mma.sync.aligned.m16n8k8.row.col.f32.tf32.tf32.f32 "
        "{%0,%1,%2,%3},{%4,%5,%6,%7},{%8,%9},{%0,%1,%2,%3};"
        : "+f"(d[0]), "+f"(d[1]), "+f"(d[2]), "+f"(d[3])
        : "r"(a[0]), "r"(a[1]), "r"(a[2]), "r"(a[3]), "r"(b[0]), "r"(b[1]));
}

// ---------------------------------------------------------------------------
// tf32 tensor-core GEMM: C[M,N] = A[M,K] @ B[N,K]^T + bias[N]
// 128x128 block tile, BK=16, 256 threads (8 warps, 2M x 4N), warp tile 64x32.
// smem padded stride 20 -> conflict-free fragment LDS.
// ---------------------------------------------------------------------------
#define GST 20
__global__ void __launch_bounds__(256) gemm_tf32_kernel(
    const float* __restrict__ A, const float* __restrict__ Bm,
    const float* __restrict__ bias, float* __restrict__ C,
    int M, int N, int K)
{
    __shared__ float As[2][128 * GST];
    __shared__ float Bs[2][128 * GST];
    const int tid  = threadIdx.x;
    const int lane = tid & 31;
    const int wid  = tid >> 5;
    const int wm   = wid & 1;        // 0..1
    const int wn   = wid >> 1;       // 0..3
    const int m0 = blockIdx.y * 128;
    const int n0 = blockIdx.x * 128;
    const int lr  = tid >> 1;
    const int lk8 = (tid & 1) * 8;
    const float* Ap = A  + (size_t)(m0 + lr) * K + lk8;
    const float* Bp = Bm + (size_t)(n0 + lr) * K + lk8;
    const int gid = lane >> 2;       // groupID
    const int tig = lane & 3;        // thread in group

    float acc[4][4][4];
#pragma unroll
    for (int i = 0; i < 4; i++)
#pragma unroll
        for (int j = 0; j < 4; j++)
#pragma unroll
            for (int r = 0; r < 4; r++) acc[i][j][r] = 0.f;

    float4 a0 = *(const float4*)(Ap);
    float4 a1 = *(const float4*)(Ap + 4);
    float4 b0 = *(const float4*)(Bp);
    float4 b1 = *(const float4*)(Bp + 4);
    int buf = 0;
    {
        float* Ad = &As[0][lr * GST + lk8];
        float* Bd = &Bs[0][lr * GST + lk8];
        Ad[0]=f2tf(a0.x); Ad[1]=f2tf(a0.y); Ad[2]=f2tf(a0.z); Ad[3]=f2tf(a0.w);
        Ad[4]=f2tf(a1.x); Ad[5]=f2tf(a1.y); Ad[6]=f2tf(a1.z); Ad[7]=f2tf(a1.w);
        Bd[0]=f2tf(b0.x); Bd[1]=f2tf(b0.y); Bd[2]=f2tf(b0.z); Bd[3]=f2tf(b0.w);
        Bd[4]=f2tf(b1.x); Bd[5]=f2tf(b1.y); Bd[6]=f2tf(b1.z); Bd[7]=f2tf(b1.w);
    }
    __syncthreads();

    for (int k0 = 16; k0 <= K; k0 += 16) {
        const bool more = (k0 < K);
        if (more) {
            a0 = *(const float4*)(Ap + k0);
            a1 = *(const float4*)(Ap + k0 + 4);
            b0 = *(const float4*)(Bp + k0);
            b1 = *(const float4*)(Bp + k0 + 4);
        }
        const float* Ac = As[buf];
        const float* Bc = Bs[buf];
#pragma unroll
        for (int ks = 0; ks < 16; ks += 8) {
            unsigned af[4][4], bf[4][2];
#pragma unroll
            for (int mi = 0; mi < 4; mi++) {
                int m = wm * 64 + mi * 16 + gid;
                af[mi][0] = ftou(Ac[m * GST + ks + tig]);
                af[mi][1] = ftou(Ac[(m + 8) * GST + ks + tig]);
                af[mi][2] = ftou(Ac[m * GST + ks + 4 + tig]);
                af[mi][3] = ftou(Ac[(m + 8) * GST + ks + 4 + tig]);
            }
#pragma unroll
            for (int ni = 0; ni < 4; ni++) {
                int n = wn * 32 + ni * 8 + gid;
                bf[ni][0] = ftou(Bc[n * GST + ks + tig]);
                bf[ni][1] = ftou(Bc[n * GST + ks + 4 + tig]);
            }
#pragma unroll
            for (int mi = 0; mi < 4; mi++)
#pragma unroll
                for (int ni = 0; ni < 4; ni++)
                    mma8(acc[mi][ni], af[mi], bf[ni]);
        }
        if (more) {
            buf ^= 1;
            float* Ad = &As[buf][lr * GST + lk8];
            float* Bd = &Bs[buf][lr * GST + lk8];
            Ad[0]=f2tf(a0.x); Ad[1]=f2tf(a0.y); Ad[2]=f2tf(a0.z); Ad[3]=f2tf(a0.w);
            Ad[4]=f2tf(a1.x); Ad[5]=f2tf(a1.y); Ad[6]=f2tf(a1.z); Ad[7]=f2tf(a1.w);
            Bd[0]=f2tf(b0.x); Bd[1]=f2tf(b0.y); Bd[2]=f2tf(b0.z); Bd[3]=f2tf(b0.w);
            Bd[4]=f2tf(b1.x); Bd[5]=f2tf(b1.y); Bd[6]=f2tf(b1.z); Bd[7]=f2tf(b1.w);
            __syncthreads();
        }
    }

    // Epilogue
#pragma unroll
    for (int mi = 0; mi < 4; mi++) {
        int m = m0 + wm * 64 + mi * 16 + gid;
#pragma unroll
        for (int ni = 0; ni < 4; ni++) {
            int n = n0 + wn * 32 + ni * 8 + 2 * tig;
            float bx = bias[n], by = bias[n + 1];
            float2 o0 = make_float2(acc[mi][ni][0] + bx, acc[mi][ni][1] + by);
            float2 o1 = make_float2(acc[mi][ni][2] + bx, acc[mi][ni][3] + by);
            *(float2*)(C + (size_t)m * N + n) = o0;
            *(float2*)(C + (size_t)(m + 8) * N + n) = o1;
        }
    }
}

// ---------------------------------------------------------------------------
// Flash attention (unchanged from R2). One block = (b,h,q-tile of 64).
// ---------------------------------------------------------------------------
__global__ void __launch_bounds__(128) flash_kernel(const float* __restrict__ td_ptr)
{
    extern __shared__ float sm[];
    float* Qs = sm;
    float* Ksb = sm + 4096;
    float* Vsb = sm + 12288;
    float* Ps = sm + 20480;

    const int tid = threadIdx.x;
    const int bh = blockIdx.x;
    const int qt = blockIdx.y;
    const int b  = bh >> 4;
    const int h  = bh & 15;
    const int tx = tid & 15;
    const int ty = tid >> 4;
    const float atd = fabsf(*td_ptr);
    const float scale = 0.125f;

    {
        const float* qbase = g_qkv + (size_t)(b * S_ + qt * 64) * D3_ + h * HD_;
#pragma unroll
        for (int l = 0; l < 8; l++) {
            int lin = tid + l * 128;
            int r = lin >> 4;
            int u = lin & 15;
            *(float4*)&Qs[r * 64 + u * 4] = *(const float4*)(qbase + (size_t)r * D3_ + u * 4);
        }
    }

    auto issue = [&](int kt, int bf) {
        const float* kb = g_qkv + (size_t)(b * S_ + kt * 64) * D3_ + D_ + h * HD_;
        const float* vb = kb + D_;
        float* Kd = Ksb + bf * 4096;
        float* Vd = Vsb + bf * 4096;
#pragma unroll
        for (int l = 0; l < 8; l++) {
            int lin = tid + l * 128;
            int r = lin >> 4;
            int u = lin & 15;
            cpa16(su32(&Kd[r * 64 + ((u ^ ((r >> 2) & 7)) << 2)]), kb + (size_t)r * D3_ + u * 4);
            cpa16(su32(&Vd[r * 64 + u * 4]), vb + (size_t)r * D3_ + u * 4);
        }
        CP_COMMIT();
    };

    issue(0, 0);

    float m[8], lsum[8], acc[8][4];
#pragma unroll
    for (int qi = 0; qi < 8; qi++) {
        m[qi] = -1e30f; lsum[qi] = 0.f;
#pragma unroll
        for (int j = 0; j < 4; j++) acc[qi][j] = 0.f;
    }

    for (int kt = 0; kt < 16; kt++) {
        CP_WAIT0();
        __syncthreads();
        if (kt < 15) issue(kt + 1, (kt + 1) & 1);

        const float* Kc = Ksb + (kt & 1) * 4096;
        const float* Vc = Vsb + (kt & 1) * 4096;

        float s[8][4];
#pragma unroll
        for (int qi = 0; qi < 8; qi++)
#pragma unroll
            for (int j = 0; j < 4; j++) s[qi][j] = 0.f;

#pragma unroll
        for (int d4 = 0; d4 < 64; d4 += 4) {
            int u = d4 >> 2;
            float4 kf[4];
#pragma unroll
            for (int i = 0; i < 4; i++)
                kf[i] = *(const float4*)&Kc[(tx * 4 + i) * 64 + ((u ^ (tx & 7)) << 2)];
#pragma unroll
            for (int qi = 0; qi < 8; qi++) {
                float4 qf = *(const float4*)&Qs[(ty * 8 + qi) * 64 + d4];
#pragma unroll
                for (int i = 0; i < 4; i++)
                    s[qi][i] += qf.x * kf[i].x + qf.y * kf[i].y +
                                qf.z * kf[i].z + qf.w * kf[i].w;
            }
        }

#pragma unroll
        for (int qi = 0; qi < 8; qi++) {
            int qg = qt * 64 + ty * 8 + qi;
            float mloc = -1e30f;
#pragma unroll
            for (int i = 0; i < 4; i++) {
                int kg = kt * 64 + tx * 4 + i;
                float val = s[qi][i] * scale - atd * fabsf((float)(qg - kg));
                s[qi][i] = val;
                mloc = fmaxf(mloc, val);
            }
#pragma unroll
            for (int o = 8; o >= 1; o >>= 1)
                mloc = fmaxf(mloc, __shfl_xor_sync(0xffffffffu, mloc, o));
            float mnew = fmaxf(m[qi], mloc);
            float corr = __expf(m[qi] - mnew);
            lsum[qi] *= corr;
#pragma unroll
            for (int j = 0; j < 4; j++) acc[qi][j] *= corr;
            float psum = 0.f;
#pragma unroll
            for (int i = 0; i < 4; i++) {
                float p = __expf(s[qi][i] - mnew);
                s[qi][i] = p;
                psum += p;
            }
#pragma unroll
            for (int o = 8; o >= 1; o >>= 1)
                psum += __shfl_xor_sync(0xffffffffu, psum, o);
            lsum[qi] += psum;
            m[qi] = mnew;
            *(float4*)&Ps[(ty * 8 + qi) * 64 + tx * 4] =
                make_float4(s[qi][0], s[qi][1], s[qi][2], s[qi][3]);
        }
        __syncthreads();

#pragma unroll
        for (int k4 = 0; k4 < 64; k4 += 4) {
            float4 vf[4];
#pragma unroll
            for (int i = 0; i < 4; i++)
                vf[i] = *(const float4*)&Vc[(k4 + i) * 64 + tx * 4];
#pragma unroll
            for (int qi = 0; qi < 8; qi++) {
                float4 pf = *(const float4*)&Ps[(ty * 8 + qi) * 64 + k4];
                acc[qi][0] += pf.x * vf[0].x + pf.y * vf[1].x + pf.z * vf[2].x + pf.w * vf[3].x;
                acc[qi][1] += pf.x * vf[0].y + pf.y * vf[1].y + pf.z * vf[2].y + pf.w * vf[3].y;
                acc[qi][2] += pf.x * vf[0].z + pf.y * vf[1].z + pf.z * vf[2].z + pf.w * vf[3].z;
                acc[qi][3] += pf.x * vf[0].w + pf.y * vf[1].w + pf.z * vf[2].w + pf.w * vf[3].w;
            }
        }
    }

#pragma unroll
    for (int qi = 0; qi < 8; qi++) {
        float inv = 1.f / lsum[qi];
        int t = b * S_ + qt * 64 + ty * 8 + qi;
        float4 o4;
        o4.x = acc[qi][0] * inv; o4.y = acc[qi][1] * inv;
        o4.z = acc[qi][2] * inv; o4.w = acc[qi][3] * inv;
        *(float4*)&g_attn[(size_t)t * D_ + h * HD_ + tx * 4] = o4;
        if (tx == 0) {
            int si = (b * H_ + h) * S_ + qt * 64 + ty * 8 + qi;
            g_m[si] = m[qi];
            g_linv[si] = inv;
        }
    }
}

// ---------------------------------------------------------------------------
// Head-mean weights via tf32 MMA. Block = (qt,b,kt), 128 threads (4 warps),
// warp w owns score columns [w*16, w*16+16). cp.async double-buffered heads.
// Dyn smem: Q[2][64*68] K[2][64*68] ms[2][64] ls[2][64]
// ---------------------------------------------------------------------------
#define WST 68
__global__ void __launch_bounds__(128) weights_kernel(
    const float* __restrict__ td_ptr, float* __restrict__ wout)
{
    extern __shared__ float sm[];
    float* Qb = sm;                       // 2 x 4352
    float* Kb = sm + 2 * 64 * WST;        // 2 x 4352
    float* msb = sm + 4 * 64 * WST;       // 2 x 64
    float* lsb = msb + 128;               // 2 x 64

    const int tid  = threadIdx.x;
    const int lane = tid & 31;
    const int wid  = tid >> 5;            // 0..3
    const int qt = blockIdx.x;
    const int b  = blockIdx.y;
    const int kt = blockIdx.z;
    const float atd = fabsf(*td_ptr);
    const float scale = 0.125f;
    const int gid = lane >> 2;
    const int tig = lane & 3;

    auto issue = [&](int h, int bf) {
        const float* qb = g_qkv + (size_t)(b * S_ + qt * 64) * D3_ + h * HD_;
        const float* kb = g_qkv + (size_t)(b * S_ + kt * 64) * D3_ + D_ + h * HD_;
        float* Qd = Qb + bf * 64 * WST;
        float* Kd = Kb + bf * 64 * WST;
#pragma unroll
        for (int l = 0; l < 8; l++) {
            int lin = tid + l * 128;
            int r = lin >> 4;
            int u = lin & 15;
            cpa16(su32(&Qd[r * WST + u * 4]), qb + (size_t)r * D3_ + u * 4);
            cpa16(su32(&Kd[r * WST + u * 4]), kb + (size_t)r * D3_ + u * 4);
        }
        CP_COMMIT();
    };

    issue(0, 0);
    // stage m/linv for head 0
    {
        int si0 = (b * H_ + 0) * S_ + qt * 64;
        if (tid < 64) msb[tid] = g_m[si0 + tid];
        else          lsb[tid - 64] = g_linv[si0 + tid - 64];
    }

    float wsum[4][2][4];
#pragma unroll
    for (int mi = 0; mi < 4; mi++)
#pragma unroll
        for (int ni = 0; ni < 2; ni++)
#pragma unroll
            for (int r = 0; r < 4; r++) wsum[mi][ni][r] = 0.f;

    for (int h = 0; h < H_; h++) {
        const int bf = h & 1;
        CP_WAIT0();
        __syncthreads();
        if (h < 15) {
            issue(h + 1, bf ^ 1);
            int si0 = (b * H_ + h + 1) * S_ + qt * 64;
            if (tid < 64) msb[(bf ^ 1) * 64 + tid] = g_m[si0 + tid];
            else          lsb[(bf ^ 1) * 64 + tid - 64] = g_linv[si0 + tid - 64];
        }
        const float* Qc = Qb + bf * 64 * WST;
        const float* Kc = Kb + bf * 64 * WST;
        const float* ms = msb + bf * 64;
        const float* ls = lsb + bf * 64;

        float acc[4][2][4];
#pragma unroll
        for (int mi = 0; mi < 4; mi++)
#pragma unroll
            for (int ni = 0; ni < 2; ni++)
#pragma unroll
                for (int r = 0; r < 4; r++) acc[mi][ni][r] = 0.f;

#pragma unroll
        for (int ks = 0; ks < 64; ks += 8) {
            unsigned af[4][4], bfr[2][2];
#pragma unroll
            for (int mi = 0; mi < 4; mi++) {
                int m = mi * 16 + gid;
                af[mi][0] = ftou(f2tf(Qc[m * WST + ks + tig]));
                af[mi][1] = ftou(f2tf(Qc[(m + 8) * WST + ks + tig]));
                af[mi][2] = ftou(f2tf(Qc[m * WST + ks + 4 + tig]));
                af[mi][3] = ftou(f2tf(Qc[(m + 8) * WST + ks + 4 + tig]));
            }
#pragma unroll
            for (int ni = 0; ni < 2; ni++) {
                int n = wid * 16 + ni * 8 + gid;
                bfr[ni][0] = ftou(f2tf(Kc[n * WST + ks + tig]));
                bfr[ni][1] = ftou(f2tf(Kc[n * WST + ks + 4 + tig]));
            }
#pragma unroll
            for (int mi = 0; mi < 4; mi++)
#pragma unroll
                for (int ni = 0; ni < 2; ni++)
                    mma8(acc[mi][ni], af[mi], bfr[ni]);
        }

        // exp epilogue in fragment layout
#pragma unroll
        for (int mi = 0; mi < 4; mi++) {
            int r0 = mi * 16 + gid;
            int r1 = r0 + 8;
            int qg0 = qt * 64 + r0;
            int qg1 = qt * 64 + r1;
            float m0v = ms[r0], l0v = ls[r0];
            float m1v = ms[r1], l1v = ls[r1];
#pragma unroll
            for (int ni = 0; ni < 2; ni++) {
                int c0 = kt * 64 + wid * 16 + ni * 8 + 2 * tig;
                float v;
                v = acc[mi][ni][0] * scale - atd * fabsf((float)(qg0 - c0));
                wsum[mi][ni][0] += __expf(v - m0v) * l0v;
                v = acc[mi][ni][1] * scale - atd * fabsf((float)(qg0 - c0 - 1));
                wsum[mi][ni][1] += __expf(v - m0v) * l0v;
                v = acc[mi][ni][2] * scale - atd * fabsf((float)(qg1 - c0));
                wsum[mi][ni][2] += __expf(v - m1v) * l1v;
                v = acc[mi][ni][3] * scale - atd * fabsf((float)(qg1 - c0 - 1));
                wsum[mi][ni][3] += __expf(v - m1v) * l1v;
            }
        }
    }

    const float inv_h = 1.0f / (float)H_;
#pragma unroll
    for (int mi = 0; mi < 4; mi++) {
        int r0 = qt * 64 + mi * 16 + gid;
#pragma unroll
        for (int ni = 0; ni < 2; ni++) {
            int c = kt * 64 + wid * 16 + ni * 8 + 2 * tig;
            float2 o0 = make_float2(wsum[mi][ni][0] * inv_h, wsum[mi][ni][1] * inv_h);
            float2 o1 = make_float2(wsum[mi][ni][2] * inv_h, wsum[mi][ni][3] * inv_h);
            *(float2*)(wout + (size_t)(b * S_ + r0) * S_ + c) = o0;
            *(float2*)(wout + (size_t)(b * S_ + r0 + 8) * S_ + c) = o1;
        }
    }
}

// ---------------------------------------------------------------------------
// Residual + LayerNorm (unchanged)
// ---------------------------------------------------------------------------
__global__ void __launch_bounds__(256) ln_kernel(
    const float* __restrict__ x, const float* __restrict__ lnw,
    const float* __restrict__ lnb, float* __restrict__ out)
{
    const int row = blockIdx.x;
    const int tid = threadIdx.x;
    const float* xr = x + (size_t)row * D_;
    const float* ar = g_attnout + (size_t)row * D_;

    float4 xv = *(const float4*)(xr + tid * 4);
    float4 av = *(const float4*)(ar + tid * 4);
    float y[4];
    y[0] = xv.x + av.x; y[1] = xv.y + av.y;
    y[2] = xv.z + av.z; y[3] = xv.w + av.w;

    float s  = y[0] + y[1] + y[2] + y[3];
    float sq = y[0]*y[0] + y[1]*y[1] + y[2]*y[2] + y[3]*y[3];
#pragma unroll
    for (int o = 16; o >= 1; o >>= 1) {
        s  += __shfl_xor_sync(0xffffffffu, s,  o);
        sq += __shfl_xor_sync(0xffffffffu, sq, o);
    }
    __shared__ float red[16];
    const int wid = tid >> 5;
    if ((tid & 31) == 0) { red[wid] = s; red[8 + wid] = sq; }
    __syncthreads();
    float st = 0.f, sqt = 0.f;
#pragma unroll
    for (int w = 0; w < 8; w++) { st += red[w]; sqt += red[8 + w]; }
    float mu = st * (1.0f / D_);
    float var = sqt * (1.0f / D_) - mu * mu;
    float rstd = rsqrtf(var + 1e-5f);

    float4 wv = *(const float4*)(lnw + tid * 4);
    float4 bv = *(const float4*)(lnb + tid * 4);
    float4 o4;
    o4.x = (y[0] - mu) * rstd * wv.x + bv.x;
    o4.y = (y[1] - mu) * rstd * wv.y + bv.y;
    o4.z = (y[2] - mu) * rstd * wv.z + bv.z;
    o4.w = (y[3] - mu) * rstd * wv.w + bv.w;
    *(float4*)(out + (size_t)row * D_ + tid * 4) = o4;
}

// ---------------------------------------------------------------------------
extern "C" void kernel_launch(void* const* d_in, const int* in_sizes, int n_in,
                              void* d_out, int out_size)
{
    (void)in_sizes; (void)n_in; (void)out_size;
    const float* x     = (const float*)d_in[0];
    const float* td    = (const float*)d_in[1];
    const float* in_w  = (const float*)d_in[2];
    const float* in_b  = (const float*)d_in[3];
    const float* out_w = (const float*)d_in[4];
    const float* out_b = (const float*)d_in[5];
    const float* lnw   = (const float*)d_in[6];
    const float* lnb   = (const float*)d_in[7];
    float* out  = (float*)d_out;
    float* wout = out + (size_t)T_ * D_;

    float *qkv_p, *attn_p, *attnout_p;
    cudaGetSymbolAddress((void**)&qkv_p, g_qkv);
    cudaGetSymbolAddress((void**)&attn_p, g_attn);
    cudaGetSymbolAddress((void**)&attnout_p, g_attnout);

    cudaFuncSetAttribute(flash_kernel, cudaFuncAttributeMaxDynamicSharedMemorySize, 96 * 1024);
    const int wsmem = (4 * 64 * WST + 256) * 4;
    cudaFuncSetAttribute(weights_kernel, cudaFuncAttributeMaxDynamicSharedMemorySize, wsmem);

    // 1. QKV projection [8192, 3072]
    gemm_tf32_kernel<<<dim3(3 * D_ / 128, T_ / 128), 256>>>(
        x, in_w, in_b, qkv_p, T_, 3 * D_, D_);

    // 2. Flash attention -> g_attn, stats
    flash_kernel<<<dim3(B_ * H_, S_ / 64), 128, 96 * 1024>>>(td);

    // 3. Head-mean weights -> second output
    weights_kernel<<<dim3(S_ / 64, B_, S_ / 64), 128, wsmem>>>(td, wout);

    // 4. Out projection [8192, 1024]
    gemm_tf32_kernel<<<dim3(D_ / 128, T_ / 128), 256>>>(
        attn_p, out_w, out_b, attnout_p, T_, D_, D_);

    // 5. Residual + LayerNorm
    ln_kernel<<<T_, 256>>>(x, lnw, lnb, out);
}

// round 4
// speedup vs baseline: 3.4335x; 1.7032x over previous
#include <cuda_runtime.h>

// Problem constants
#define S_   1024
#define B_   8
#define D_   1024
#define H_   16
#define HD_  64
#define T_   (B_ * S_)
#define D3_  (3 * D_)

// Scratch
__device__ float g_qkv[(size_t)T_ * 3 * D_];
__device__ float g_attn[(size_t)T_ * D_];
__device__ float g_attnout[(size_t)T_ * D_];
__device__ float g_m[B_ * H_ * S_];
__device__ float g_linv[B_ * H_ * S_];

__device__ __forceinline__ unsigned su32(const void* p) {
    return (unsigned)__cvta_generic_to_shared(p);
}
__device__ __forceinline__ void cpa16(unsigned dst, const float* src) {
    asm volatile("cp.async.cg.shared.global [%0], [%1], 16;" :: "r"(dst), "l"(src));
}
#define CP_COMMIT() asm volatile("cp.async.commit_group;")
#define CP_WAIT0()  asm volatile("cp.async.wait_group 0;")
#define CP_WAIT2()  asm volatile("cp.async.wait_group 2;")

__device__ __forceinline__ float f2tf(float x) {
    unsigned r;
    asm("cvt.rna.tf32.f32 %0, %1;" : "=r"(r) : "f"(x));
    return __uint_as_float(r);
}
__device__ __forceinline__ unsigned ftou(float x) { return __float_as_uint(x); }
__device__ __forceinline__ unsigned cvttf(float x) {
    unsigned r;
    asm("cvt.rna.tf32.f32 %0, %1;" : "=r"(r) : "f"(x));
    return r;
}

__device__ __forceinline__ void mma8(float* d, const unsigned* a, const unsigned* b) {
    asm volatile(
        "mma.sync.aligned.m16n8k8.row.col.f32.tf32.tf32.f32 "
        "{%0,%1,%2,%3},{%4,%5,%6,%7},{%8,%9},{%0,%1,%2,%3};"
        : "+f"(d[0]), "+f"(d[1]), "+f"(d[2]), "+f"(d[3])
        : "r"(a[0]), "r"(a[1]), "r"(a[2]), "r"(a[3]), "r"(b[0]), "r"(b[1]));
}

// ---------------------------------------------------------------------------
// tf32 GEMM, cp.async 3-stage: C[M,N] = A[M,K] @ B[N,K]^T + bias[N]
// 128x128 tile, BK=16, 256 threads (2x4 warps), warp tile 64x32.
// fp32 in smem; cvt.rna at fragment load. ROUND_OUT rounds C to tf32.
// ---------------------------------------------------------------------------
#define GST 20
template<bool ROUND_OUT>
__global__ void __launch_bounds__(256) gemm_tf32_kernel(
    const float* __restrict__ A, const float* __restrict__ Bm,
    const float* __restrict__ bias, float* __restrict__ C,
    int M, int N, int K)
{
    extern __shared__ float sm[];
    float* Asm = sm;                 // 3 x 2560
    float* Bsm = sm + 3 * 128 * GST; // 3 x 2560

    const int tid  = threadIdx.x;
    const int lane = tid & 31;
    const int wid  = tid >> 5;
    const int wm   = wid & 1;
    const int wn   = wid >> 1;
    const int m0 = blockIdx.y * 128;
    const int n0 = blockIdx.x * 128;
    const int lr  = tid >> 1;
    const int lk8 = (tid & 1) * 8;
    const float* Ap = A  + (size_t)(m0 + lr) * K + lk8;
    const float* Bp = Bm + (size_t)(n0 + lr) * K + lk8;
    const int gid = lane >> 2;
    const int tig = lane & 3;

    auto issue = [&](int st, int k0) {
        float* Ad = Asm + st * (128 * GST) + lr * GST + lk8;
        float* Bd = Bsm + st * (128 * GST) + lr * GST + lk8;
        cpa16(su32(Ad),     Ap + k0);
        cpa16(su32(Ad + 4), Ap + k0 + 4);
        cpa16(su32(Bd),     Bp + k0);
        cpa16(su32(Bd + 4), Bp + k0 + 4);
        CP_COMMIT();
    };

    float acc[4][4][4];
#pragma unroll
    for (int i = 0; i < 4; i++)
#pragma unroll
        for (int j = 0; j < 4; j++)
#pragma unroll
            for (int r = 0; r < 4; r++) acc[i][j][r] = 0.f;

    issue(0, 0); issue(1, 16); issue(2, 32);

    const int NIT = K / 16;
    int st = 0;
    for (int i = 0; i < NIT; i++) {
        CP_WAIT2();
        __syncthreads();
        const float* Ac = Asm + st * (128 * GST);
        const float* Bc = Bsm + st * (128 * GST);
#pragma unroll
        for (int ks = 0; ks < 16; ks += 8) {
            unsigned af[4][4], bf[4][2];
#pragma unroll
            for (int mi = 0; mi < 4; mi++) {
                int m = wm * 64 + mi * 16 + gid;
                af[mi][0] = cvttf(Ac[m * GST + ks + tig]);
                af[mi][1] = cvttf(Ac[(m + 8) * GST + ks + tig]);
                af[mi][2] = cvttf(Ac[m * GST + ks + 4 + tig]);
                af[mi][3] = cvttf(Ac[(m + 8) * GST + ks + 4 + tig]);
            }
#pragma unroll
            for (int ni = 0; ni < 4; ni++) {
                int n = wn * 32 + ni * 8 + gid;
                bf[ni][0] = cvttf(Bc[n * GST + ks + tig]);
                bf[ni][1] = cvttf(Bc[n * GST + ks + 4 + tig]);
            }
#pragma unroll
            for (int mi = 0; mi < 4; mi++)
#pragma unroll
                for (int ni = 0; ni < 4; ni++)
                    mma8(acc[mi][ni], af[mi], bf[ni]);
        }
        __syncthreads();
        if (i + 3 < NIT) issue(st, (i + 3) * 16);
        st = (st == 2) ? 0 : st + 1;
    }

#pragma unroll
    for (int mi = 0; mi < 4; mi++) {
        int m = m0 + wm * 64 + mi * 16 + gid;
#pragma unroll
        for (int ni = 0; ni < 4; ni++) {
            int n = n0 + wn * 32 + ni * 8 + 2 * tig;
            float bx = bias[n], by = bias[n + 1];
            float2 o0, o1;
            if (ROUND_OUT) {
                o0 = make_float2(f2tf(acc[mi][ni][0] + bx), f2tf(acc[mi][ni][1] + by));
                o1 = make_float2(f2tf(acc[mi][ni][2] + bx), f2tf(acc[mi][ni][3] + by));
            } else {
                o0 = make_float2(acc[mi][ni][0] + bx, acc[mi][ni][1] + by);
                o1 = make_float2(acc[mi][ni][2] + bx, acc[mi][ni][3] + by);
            }
            *(float2*)(C + (size_t)m * N + n) = o0;
            *(float2*)(C + (size_t)(m + 8) * N + n) = o1;
        }
    }
}

// ---------------------------------------------------------------------------
// Flash attention, tensor-core. Block = (b*h, q-tile of 128), 256 thr (8 warps).
// Warp w owns q rows [w*16, w*16+16). QK^T + PV via m16n8k8 tf32.
// K swz: col^(4*(row&7)); V swz: col^(8*(row&3)); P fragment-packed per warp.
// qkv is tf32-pre-rounded -> no cvt on Q/K/V; only P needs cvt after exp.
// smem floats: Q[8192] K[2][4096] V[2][4096] P[8][1056]
// ---------------------------------------------------------------------------
__global__ void __launch_bounds__(256) flash_kernel(const float* __restrict__ td_ptr)
{
    extern __shared__ float sm[];
    float* Qs  = sm;            // 8192
    float* Ksb = sm + 8192;     // 2 x 4096
    float* Vsb = sm + 16384;    // 2 x 4096
    float* Psb = sm + 24576;    // 8 x 1056

    const int tid  = threadIdx.x;
    const int lane = tid & 31;
    const int w    = tid >> 5;       // 0..7
    const int gid  = lane >> 2;
    const int tig  = lane & 3;
    const int bh = blockIdx.x;
    const int qt = blockIdx.y;       // q-tile of 128
    const int b  = bh >> 4;
    const int h  = bh & 15;
    const float atd = fabsf(*td_ptr);
    const float scale = 0.125f;

    // Issue Q tile (group with K0/V0)
    {
        const float* qb = g_qkv + (size_t)(b * S_ + qt * 128) * D3_ + h * HD_;
#pragma unroll
        for (int l = 0; l < 8; l++) {
            int lin = tid + l * 256;
            int r = lin >> 4;
            int u = lin & 15;
            cpa16(su32(&Qs[r * 64 + ((4 * u) ^ (4 * (r & 7)))]),
                  qb + (size_t)r * D3_ + u * 4);
        }
    }
    auto issueKV = [&](int kt, int bf) {
        const float* kb = g_qkv + (size_t)(b * S_ + kt * 64) * D3_ + D_ + h * HD_;
        const float* vb = kb + D_;
        float* Kd = Ksb + bf * 4096;
        float* Vd = Vsb + bf * 4096;
#pragma unroll
        for (int l = 0; l < 4; l++) {
            int lin = tid + l * 256;
            int r = lin >> 4;
            int u = lin & 15;
            cpa16(su32(&Kd[r * 64 + ((4 * u) ^ (4 * (r & 7)))]), kb + (size_t)r * D3_ + u * 4);
            cpa16(su32(&Vd[r * 64 + ((4 * u) ^ (8 * (r & 3)))]), vb + (size_t)r * D3_ + u * 4);
        }
        CP_COMMIT();
    };

    issueKV(0, 0);
    CP_WAIT0();
    __syncthreads();

    // Hoist Q fragments (tf32 bits already)
    unsigned qf[8][4];
#pragma unroll
    for (int s = 0; s < 8; s++) {
        int r0 = w * 16 + gid;
        qf[s][0] = ftou(Qs[r0 * 64 + ((s * 8 + tig) ^ (4 * gid))]);
        qf[s][1] = ftou(Qs[(r0 + 8) * 64 + ((s * 8 + tig) ^ (4 * gid))]);
        qf[s][2] = ftou(Qs[r0 * 64 + ((s * 8 + tig + 4) ^ (4 * gid))]);
        qf[s][3] = ftou(Qs[(r0 + 8) * 64 + ((s * 8 + tig + 4) ^ (4 * gid))]);
    }

    float oacc[8][4];
#pragma unroll
    for (int n = 0; n < 8; n++)
#pragma unroll
        for (int r = 0; r < 4; r++) oacc[n][r] = 0.f;
    float m0 = -1e30f, m1 = -1e30f, ls0 = 0.f, ls1 = 0.f;

    const float qg0f = (float)(qt * 128 + w * 16 + gid);
    const float qg1f = qg0f + 8.f;
    float* Pw = Psb + w * 1056;

    for (int kt = 0; kt < 16; kt++) {
        CP_WAIT0();
        __syncthreads();
        if (kt < 15) issueKV(kt + 1, (kt + 1) & 1);
        const float* Kc = Ksb + (kt & 1) * 4096;
        const float* Vc = Vsb + (kt & 1) * 4096;

        // S = Q @ K^T  (per warp: 16 x 64)
        float sacc[8][4];
#pragma unroll
        for (int n = 0; n < 8; n++)
#pragma unroll
            for (int r = 0; r < 4; r++) sacc[n][r] = 0.f;
#pragma unroll
        for (int s = 0; s < 8; s++) {
            unsigned kb[8][2];
#pragma unroll
            for (int nb = 0; nb < 8; nb++) {
                int row = nb * 8 + gid;
                kb[nb][0] = ftou(Kc[row * 64 + ((s * 8 + tig) ^ (4 * gid))]);
                kb[nb][1] = ftou(Kc[row * 64 + ((s * 8 + tig + 4) ^ (4 * gid))]);
            }
#pragma unroll
            for (int nb = 0; nb < 8; nb++)
                mma8(sacc[nb], qf[s], kb[nb]);
        }

        // bias + row max
        float mx0 = -1e30f, mx1 = -1e30f;
#pragma unroll
        for (int nb = 0; nb < 8; nb++) {
            float c0 = (float)(kt * 64 + nb * 8 + 2 * tig);
            sacc[nb][0] = sacc[nb][0] * scale - atd * fabsf(qg0f - c0);
            sacc[nb][1] = sacc[nb][1] * scale - atd * fabsf(qg0f - c0 - 1.f);
            sacc[nb][2] = sacc[nb][2] * scale - atd * fabsf(qg1f - c0);
            sacc[nb][3] = sacc[nb][3] * scale - atd * fabsf(qg1f - c0 - 1.f);
            mx0 = fmaxf(mx0, fmaxf(sacc[nb][0], sacc[nb][1]));
            mx1 = fmaxf(mx1, fmaxf(sacc[nb][2], sacc[nb][3]));
        }
#pragma unroll
        for (int o = 1; o <= 2; o <<= 1) {
            mx0 = fmaxf(mx0, __shfl_xor_sync(0xffffffffu, mx0, o));
            mx1 = fmaxf(mx1, __shfl_xor_sync(0xffffffffu, mx1, o));
        }
        float mn0 = fmaxf(m0, mx0), mn1 = fmaxf(m1, mx1);
        float cr0 = __expf(m0 - mn0), cr1 = __expf(m1 - mn1);
        m0 = mn0; m1 = mn1;

        // exp + P store (fragment-packed) + partial sums
        float ps0 = 0.f, ps1 = 0.f;
#pragma unroll
        for (int nb = 0; nb < 8; nb++) {
            float p00 = __expf(sacc[nb][0] - m0);
            float p01 = __expf(sacc[nb][1] - m0);
            float p10 = __expf(sacc[nb][2] - m1);
            float p11 = __expf(sacc[nb][3] - m1);
            ps0 += p00 + p01; ps1 += p10 + p11;
            int base = nb * 132 + (tig >> 1) * 64 + gid * 4 + 2 * (tig & 1);
            *(float2*)&Pw[base]      = make_float2(f2tf(p00), f2tf(p01));
            *(float2*)&Pw[base + 32] = make_float2(f2tf(p10), f2tf(p11));
        }
#pragma unroll
        for (int o = 1; o <= 2; o <<= 1) {
            ps0 += __shfl_xor_sync(0xffffffffu, ps0, o);
            ps1 += __shfl_xor_sync(0xffffffffu, ps1, o);
        }
        ls0 = ls0 * cr0 + ps0;
        ls1 = ls1 * cr1 + ps1;
#pragma unroll
        for (int nb = 0; nb < 8; nb++) {
            oacc[nb][0] *= cr0; oacc[nb][1] *= cr0;
            oacc[nb][2] *= cr1; oacc[nb][3] *= cr1;
        }
        __syncwarp();

        // O += P @ V
#pragma unroll
        for (int s = 0; s < 8; s++) {
            unsigned pa[4];
            pa[0] = ftou(Pw[s * 132 + lane]);
            pa[1] = ftou(Pw[s * 132 + 32 + lane]);
            pa[2] = ftou(Pw[s * 132 + 64 + lane]);
            pa[3] = ftou(Pw[s * 132 + 96 + lane]);
            unsigned vb[8][2];
#pragma unroll
            for (int nb = 0; nb < 8; nb++) {
                int col = (nb * 8 + gid) ^ (8 * tig);
                vb[nb][0] = ftou(Vc[(s * 8 + tig) * 64 + col]);
                vb[nb][1] = ftou(Vc[(s * 8 + tig + 4) * 64 + col]);
            }
#pragma unroll
            for (int nb = 0; nb < 8; nb++)
                mma8(oacc[nb], pa, vb[nb]);
        }
    }

    // Epilogue
    float inv0 = 1.f / ls0, inv1 = 1.f / ls1;
    int t0 = b * S_ + qt * 128 + w * 16 + gid;
#pragma unroll
    for (int nb = 0; nb < 8; nb++) {
        int c = h * HD_ + nb * 8 + 2 * tig;
        *(float2*)&g_attn[(size_t)t0 * D_ + c] =
            make_float2(oacc[nb][0] * inv0, oacc[nb][1] * inv0);
        *(float2*)&g_attn[(size_t)(t0 + 8) * D_ + c] =
            make_float2(oacc[nb][2] * inv1, oacc[nb][3] * inv1);
    }
    if (tig == 0) {
        int si = (b * H_ + h) * S_ + qt * 128 + w * 16 + gid;
        g_m[si] = m0;       g_linv[si] = inv0;
        g_m[si + 8] = m1;   g_linv[si + 8] = inv1;
    }
}

// ---------------------------------------------------------------------------
// Head-mean weights (tf32 MMA, qkv pre-rounded -> no cvt).
// ---------------------------------------------------------------------------
#define WST 68
__global__ void __launch_bounds__(128) weights_kernel(
    const float* __restrict__ td_ptr, float* __restrict__ wout)
{
    extern __shared__ float sm[];
    float* Qb = sm;
    float* Kb = sm + 2 * 64 * WST;
    float* msb = sm + 4 * 64 * WST;
    float* lsb = msb + 128;

    const int tid  = threadIdx.x;
    const int lane = tid & 31;
    const int wid  = tid >> 5;
    const int qt = blockIdx.x;
    const int b  = blockIdx.y;
    const int kt = blockIdx.z;
    const float atd = fabsf(*td_ptr);
    const float scale = 0.125f;
    const int gid = lane >> 2;
    const int tig = lane & 3;

    auto issue = [&](int h, int bf) {
        const float* qb = g_qkv + (size_t)(b * S_ + qt * 64) * D3_ + h * HD_;
        const float* kb = g_qkv + (size_t)(b * S_ + kt * 64) * D3_ + D_ + h * HD_;
        float* Qd = Qb + bf * 64 * WST;
        float* Kd = Kb + bf * 64 * WST;
#pragma unroll
        for (int l = 0; l < 8; l++) {
            int lin = tid + l * 128;
            int r = lin >> 4;
            int u = lin & 15;
            cpa16(su32(&Qd[r * WST + u * 4]), qb + (size_t)r * D3_ + u * 4);
            cpa16(su32(&Kd[r * WST + u * 4]), kb + (size_t)r * D3_ + u * 4);
        }
        CP_COMMIT();
    };

    issue(0, 0);
    {
        int si0 = (b * H_ + 0) * S_ + qt * 64;
        if (tid < 64) msb[tid] = g_m[si0 + tid];
        else          lsb[tid - 64] = g_linv[si0 + tid - 64];
    }

    float wsum[4][2][4];
#pragma unroll
    for (int mi = 0; mi < 4; mi++)
#pragma unroll
        for (int ni = 0; ni < 2; ni++)
#pragma unroll
            for (int r = 0; r < 4; r++) wsum[mi][ni][r] = 0.f;

    for (int h = 0; h < H_; h++) {
        const int bf = h & 1;
        CP_WAIT0();
        __syncthreads();
        if (h < 15) {
            issue(h + 1, bf ^ 1);
            int si0 = (b * H_ + h + 1) * S_ + qt * 64;
            if (tid < 64) msb[(bf ^ 1) * 64 + tid] = g_m[si0 + tid];
            else          lsb[(bf ^ 1) * 64 + tid - 64] = g_linv[si0 + tid - 64];
        }
        const float* Qc = Qb + bf * 64 * WST;
        const float* Kc = Kb + bf * 64 * WST;
        const float* ms = msb + bf * 64;
        const float* ls = lsb + bf * 64;

        float acc[4][2][4];
#pragma unroll
        for (int mi = 0; mi < 4; mi++)
#pragma unroll
            for (int ni = 0; ni < 2; ni++)
#pragma unroll
                for (int r = 0; r < 4; r++) acc[mi][ni][r] = 0.f;

#pragma unroll
        for (int ks = 0; ks < 64; ks += 8) {
            unsigned af[4][4], bfr[2][2];
#pragma unroll
            for (int mi = 0; mi < 4; mi++) {
                int m = mi * 16 + gid;
                af[mi][0] = ftou(Qc[m * WST + ks + tig]);
                af[mi][1] = ftou(Qc[(m + 8) * WST + ks + tig]);
                af[mi][2] = ftou(Qc[m * WST + ks + 4 + tig]);
                af[mi][3] = ftou(Qc[(m + 8) * WST + ks + 4 + tig]);
            }
#pragma unroll
            for (int ni = 0; ni < 2; ni++) {
                int n = wid * 16 + ni * 8 + gid;
                bfr[ni][0] = ftou(Kc[n * WST + ks + tig]);
                bfr[ni][1] = ftou(Kc[n * WST + ks + 4 + tig]);
            }
#pragma unroll
            for (int mi = 0; mi < 4; mi++)
#pragma unroll
                for (int ni = 0; ni < 2; ni++)
                    mma8(acc[mi][ni], af[mi], bfr[ni]);
        }

#pragma unroll
        for (int mi = 0; mi < 4; mi++) {
            int r0 = mi * 16 + gid;
            int r1 = r0 + 8;
            int qg0 = qt * 64 + r0;
            int qg1 = qt * 64 + r1;
            float m0v = ms[r0], l0v = ls[r0];
            float m1v = ms[r1], l1v = ls[r1];
#pragma unroll
            for (int ni = 0; ni < 2; ni++) {
                int c0 = kt * 64 + wid * 16 + ni * 8 + 2 * tig;
                float v;
                v = acc[mi][ni][0] * scale - atd * fabsf((float)(qg0 - c0));
                wsum[mi][ni][0] += __expf(v - m0v) * l0v;
                v = acc[mi][ni][1] * scale - atd * fabsf((float)(qg0 - c0 - 1));
                wsum[mi][ni][1] += __expf(v - m0v) * l0v;
                v = acc[mi][ni][2] * scale - atd * fabsf((float)(qg1 - c0));
                wsum[mi][ni][2] += __expf(v - m1v) * l1v;
                v = acc[mi][ni][3] * scale - atd * fabsf((float)(qg1 - c0 - 1));
                wsum[mi][ni][3] += __expf(v - m1v) * l1v;
            }
        }
    }

    const float inv_h = 1.0f / (float)H_;
#pragma unroll
    for (int mi = 0; mi < 4; mi++) {
        int r0 = qt * 64 + mi * 16 + gid;
#pragma unroll
        for (int ni = 0; ni < 2; ni++) {
            int c = kt * 64 + wid * 16 + ni * 8 + 2 * tig;
            float2 o0 = make_float2(wsum[mi][ni][0] * inv_h, wsum[mi][ni][1] * inv_h);
            float2 o1 = make_float2(wsum[mi][ni][2] * inv_h, wsum[mi][ni][3] * inv_h);
            *(float2*)(wout + (size_t)(b * S_ + r0) * S_ + c) = o0;
            *(float2*)(wout + (size_t)(b * S_ + r0 + 8) * S_ + c) = o1;
        }
    }
}

// ---------------------------------------------------------------------------
// Residual + LayerNorm
// ---------------------------------------------------------------------------
__global__ void __launch_bounds__(256) ln_kernel(
    const float* __restrict__ x, const float* __restrict__ lnw,
    const float* __restrict__ lnb, float* __restrict__ out)
{
    const int row = blockIdx.x;
    const int tid = threadIdx.x;
    const float* xr = x + (size_t)row * D_;
    const float* ar = g_attnout + (size_t)row * D_;

    float4 xv = *(const float4*)(xr + tid * 4);
    float4 av = *(const float4*)(ar + tid * 4);
    float y[4];
    y[0] = xv.x + av.x; y[1] = xv.y + av.y;
    y[2] = xv.z + av.z; y[3] = xv.w + av.w;

    float s  = y[0] + y[1] + y[2] + y[3];
    float sq = y[0]*y[0] + y[1]*y[1] + y[2]*y[2] + y[3]*y[3];
#pragma unroll
    for (int o = 16; o >= 1; o >>= 1) {
        s  += __shfl_xor_sync(0xffffffffu, s,  o);
        sq += __shfl_xor_sync(0xffffffffu, sq, o);
    }
    __shared__ float red[16];
    const int wid = tid >> 5;
    if ((tid & 31) == 0) { red[wid] = s; red[8 + wid] = sq; }
    __syncthreads();
    float st = 0.f, sqt = 0.f;
#pragma unroll
    for (int w = 0; w < 8; w++) { st += red[w]; sqt += red[8 + w]; }
    float mu = st * (1.0f / D_);
    float var = sqt * (1.0f / D_) - mu * mu;
    float rstd = rsqrtf(var + 1e-5f);

    float4 wv = *(const float4*)(lnw + tid * 4);
    float4 bv = *(const float4*)(lnb + tid * 4);
    float4 o4;
    o4.x = (y[0] - mu) * rstd * wv.x + bv.x;
    o4.y = (y[1] - mu) * rstd * wv.y + bv.y;
    o4.z = (y[2] - mu) * rstd * wv.z + bv.z;
    o4.w = (y[3] - mu) * rstd * wv.w + bv.w;
    *(float4*)(out + (size_t)row * D_ + tid * 4) = o4;
}

// ---------------------------------------------------------------------------
extern "C" void kernel_launch(void* const* d_in, const int* in_sizes, int n_in,
                              void* d_out, int out_size)
{
    (void)in_sizes; (void)n_in; (void)out_size;
    const float* x     = (const float*)d_in[0];
    const float* td    = (const float*)d_in[1];
    const float* in_w  = (const float*)d_in[2];
    const float* in_b  = (const float*)d_in[3];
    const float* out_w = (const float*)d_in[4];
    const float* out_b = (const float*)d_in[5];
    const float* lnw   = (const float*)d_in[6];
    const float* lnb   = (const float*)d_in[7];
    float* out  = (float*)d_out;
    float* wout = out + (size_t)T_ * D_;

    float *qkv_p, *attn_p, *attnout_p;
    cudaGetSymbolAddress((void**)&qkv_p, g_qkv);
    cudaGetSymbolAddress((void**)&attn_p, g_attn);
    cudaGetSymbolAddress((void**)&attnout_p, g_attnout);

    const int gsmem = 3 * 2 * 128 * GST * 4;           // 61440
    const int fsmem = (8192 + 8192 + 8192 + 8 * 1056) * 4; // 132096
    const int wsmem = (4 * 64 * WST + 256) * 4;
    cudaFuncSetAttribute(gemm_tf32_kernel<true>,
                         cudaFuncAttributeMaxDynamicSharedMemorySize, gsmem);
    cudaFuncSetAttribute(gemm_tf32_kernel<false>,
                         cudaFuncAttributeMaxDynamicSharedMemorySize, gsmem);
    cudaFuncSetAttribute(flash_kernel,
                         cudaFuncAttributeMaxDynamicSharedMemorySize, fsmem);
    cudaFuncSetAttribute(weights_kernel,
                         cudaFuncAttributeMaxDynamicSharedMemorySize, wsmem);

    // 1. QKV projection (outputs rounded to tf32 for downstream MMA consumers)
    gemm_tf32_kernel<true><<<dim3(3 * D_ / 128, T_ / 128), 256, gsmem>>>(
        x, in_w, in_b, qkv_p, T_, 3 * D_, D_);

    // 2. Flash attention (tensor core) -> g_attn, stats
    flash_kernel<<<dim3(B_ * H_, S_ / 128), 256, fsmem>>>(td);

    // 3. Head-mean weights -> second output
    weights_kernel<<<dim3(S_ / 64, B_, S_ / 64), 128, wsmem>>>(td, wout);

    // 4. Out projection (full fp32 output)
    gemm_tf32_kernel<false><<<dim3(D_ / 128, T_ / 128), 256, gsmem>>>(
        attn_p, out_w, out_b, attnout_p, T_, D_, D_);

    // 5. Residual + LayerNorm
    ln_kernel<<<T_, 256>>>(x, lnw, lnb, out);
}